// round 13
// baseline (speedup 1.0000x reference)
#include <cuda_runtime.h>
#include <math_constants.h>

#define K_LEN 1024
#define I_LEN 8192
#define DIM   128
#define FULLM 0xffffffffu

#define NB   64      // row bands (CTAs)
#define BR   16      // rows per band
#define NCH  16      // column chunks
#define CW   512     // columns per chunk (4 warps x 128 cols)
#define DTH  128     // DP threads per CTA
#define CANARY 0x7FC00001u   // NaN payload; stored D values are always finite

// Scratch (alloc-free rule: __device__ globals)
__device__ float g_C[K_LEN * I_LEN];       // 32 MB cost matrix
__device__ float g_k2[K_LEN];
__device__ float g_x2[I_LEN];
__device__ float g_row[NB][I_LEN];         // bottom-row D of each band
__device__ unsigned g_flag[NB][NCH];       // chunk-done flags

// ---------------------------------------------------------------------------
// Kernel 1: squared row norms + zero the wavefront flags.
// ---------------------------------------------------------------------------
__global__ void norms_kernel(const float* __restrict__ kern,
                             const float* __restrict__ x) {
    int gtid = blockIdx.x * blockDim.x + threadIdx.x;
    if (gtid < NB * NCH) ((unsigned*)g_flag)[gtid] = 0u;

    int warp = gtid >> 5;
    int lane = threadIdx.x & 31;
    if (warp >= K_LEN + I_LEN) return;
    const float* row = (warp < K_LEN) ? (kern + warp * DIM)
                                      : (x + (warp - K_LEN) * DIM);
    float4 v = ((const float4*)row)[lane];
    float s = v.x * v.x + v.y * v.y + v.z * v.z + v.w * v.w;
#pragma unroll
    for (int off = 16; off; off >>= 1) s += __shfl_xor_sync(FULLM, s, off);
    if (lane == 0) {
        if (warp < K_LEN) g_k2[warp] = s;
        else              g_x2[warp - K_LEN] = s;
    }
}

// ---------------------------------------------------------------------------
// Kernel 2: C[m][n] = max(k2[m] + x2[n] - 2*<kern_m, x_n>, 0)   (R7 version)
// ---------------------------------------------------------------------------
#define BM 128
#define BN 128
#define BK 8

__global__ __launch_bounds__(256, 2) void cost_gemm(const float* __restrict__ A,
                                                    const float* __restrict__ B) {
    __shared__ float As[2][BK][BM + 4];
    __shared__ float Bs[2][BK][BN + 4];
    const int tid = threadIdx.x;
    const int m0 = blockIdx.y * BM;
    const int n0 = blockIdx.x * BN;
    const int lr = tid >> 1;
    const int lc = (tid & 1) * 4;
    const int tx = tid & 15;
    const int ty = tid >> 4;

    float acc[8][8];
#pragma unroll
    for (int i = 0; i < 8; i++)
#pragma unroll
        for (int j = 0; j < 8; j++) acc[i][j] = 0.0f;

    {
        float4 va = *(const float4*)(A + (size_t)(m0 + lr) * DIM + lc);
        float4 vb = *(const float4*)(B + (size_t)(n0 + lr) * DIM + lc);
        As[0][lc + 0][lr] = va.x; As[0][lc + 1][lr] = va.y;
        As[0][lc + 2][lr] = va.z; As[0][lc + 3][lr] = va.w;
        Bs[0][lc + 0][lr] = vb.x; Bs[0][lc + 1][lr] = vb.y;
        Bs[0][lc + 2][lr] = vb.z; Bs[0][lc + 3][lr] = vb.w;
    }
    __syncthreads();

    int buf = 0;
    for (int k0 = 0; k0 < DIM; k0 += BK) {
        const bool has_next = (k0 + BK < DIM);
        float4 na, nb;
        if (has_next) {
            na = *(const float4*)(A + (size_t)(m0 + lr) * DIM + k0 + BK + lc);
            nb = *(const float4*)(B + (size_t)(n0 + lr) * DIM + k0 + BK + lc);
        }
#pragma unroll
        for (int k = 0; k < BK; k++) {
            float a[8], b[8];
            *(float4*)(a)     = *(const float4*)&As[buf][k][ty * 8];
            *(float4*)(a + 4) = *(const float4*)&As[buf][k][ty * 8 + 4];
            *(float4*)(b)     = *(const float4*)&Bs[buf][k][tx * 8];
            *(float4*)(b + 4) = *(const float4*)&Bs[buf][k][tx * 8 + 4];
#pragma unroll
            for (int i = 0; i < 8; i++)
#pragma unroll
                for (int j = 0; j < 8; j++)
                    acc[i][j] += a[i] * b[j];
        }
        if (has_next) {
            const int nbuf = buf ^ 1;
            As[nbuf][lc + 0][lr] = na.x; As[nbuf][lc + 1][lr] = na.y;
            As[nbuf][lc + 2][lr] = na.z; As[nbuf][lc + 3][lr] = na.w;
            Bs[nbuf][lc + 0][lr] = nb.x; Bs[nbuf][lc + 1][lr] = nb.y;
            Bs[nbuf][lc + 2][lr] = nb.z; Bs[nbuf][lc + 3][lr] = nb.w;
            __syncthreads();
            buf = nbuf;
        }
    }

    float x2v[8];
#pragma unroll
    for (int j = 0; j < 8; j++) x2v[j] = g_x2[n0 + tx * 8 + j];
#pragma unroll
    for (int i = 0; i < 8; i++) {
        const int m = m0 + ty * 8 + i;
        const float k2 = g_k2[m];
        float4 o0, o1;
        o0.x = fmaxf(k2 + x2v[0] - 2.0f * acc[i][0], 0.0f);
        o0.y = fmaxf(k2 + x2v[1] - 2.0f * acc[i][1], 0.0f);
        o0.z = fmaxf(k2 + x2v[2] - 2.0f * acc[i][2], 0.0f);
        o0.w = fmaxf(k2 + x2v[3] - 2.0f * acc[i][3], 0.0f);
        o1.x = fmaxf(k2 + x2v[4] - 2.0f * acc[i][4], 0.0f);
        o1.y = fmaxf(k2 + x2v[5] - 2.0f * acc[i][5], 0.0f);
        o1.z = fmaxf(k2 + x2v[6] - 2.0f * acc[i][6], 0.0f);
        o1.w = fmaxf(k2 + x2v[7] - 2.0f * acc[i][7], 0.0f);
        float* dst = g_C + (size_t)m * I_LEN + n0 + tx * 8;
        *(float4*)(dst)     = o0;
        *(float4*)(dst + 4) = o1;
    }
}

// ---------------------------------------------------------------------------
// Kernel 3: block-wavefront DTW DP with warp-skewed chunks.
// CTA b owns rows [BR*b, BR*b+BR). Within a chunk of 512 cols, warp w owns
// cols [128w, 128w+128) and processes all BR rows; the left boundary at row r
// comes from warp w-1 via a write-once canary-tagged volatile smem slot
// (warps self-skew ~1 row; NO barriers in the row loop). Intra-warp left
// dependency: (C,E) pair-scan over 32 lanes. Cross-CTA: per-chunk flag.
// ---------------------------------------------------------------------------
__global__ __launch_bounds__(DTH, 1) void dtw_wave(float* __restrict__ out,
                                                   int out_size) {
    __shared__ volatile unsigned slot[3][BR];  // warp w-1 -> w handoff
    __shared__ float Dl[2][BR];                // chunk right edge, ping-pong
    const float INF = CUDART_INF_F;
    const int b    = blockIdx.x;
    const int tid  = threadIdx.x;
    const int lane = tid & 31;
    const int w    = tid >> 5;

    if (b == 0)
        for (int i = tid; i < out_size; i += DTH)
            if (i > 0) out[i] = 0.0f;
    if (tid < BR) Dl[0][tid] = INF;   // chunk 0 has no left neighbor

    float res = INF;

    for (int j = 0; j < NCH; j++) {
        const int sel = j & 1;
        if (b > 0 && tid == 0) {
            unsigned v;
            do {
                asm volatile("ld.acquire.gpu.global.u32 %0, [%1];"
                             : "=r"(v) : "l"(&g_flag[b - 1][j]));
            } while (!v);
        }
        if (tid < 3 * BR) ((volatile unsigned*)slot)[tid] = CANARY;
        __syncthreads();

        const int colbase = j * CW + 128 * w + 4 * lane;   // global column

        // top boundary (row above the band) for this warp's 4 columns
        float Dp0, Dp1, Dp2, Dp3;
        if (b > 0) {
            float4 tv = *(const float4*)(&g_row[b - 1][colbase]);
            Dp0 = tv.x; Dp1 = tv.y; Dp2 = tv.z; Dp3 = tv.w;
        } else {
            Dp0 = Dp1 = Dp2 = Dp3 = INF;
        }
        float lastD3 = Dp3;      // prev row's D3 (row -1 = top boundary)

        // warp-left diagonal D[row-1][segleft-1] for lane 0's e0 at r=0
        float bprev;
        if (w == 0) {
            if (b > 0) bprev = (j > 0) ? g_row[b - 1][j * CW - 1] : INF;
            else       bprev = (j == 0) ? 0.0f : INF;    // D[-1][-1] = 0
        } else {
            bprev = (b > 0) ? g_row[b - 1][j * CW + 128 * w - 1] : INF;
        }

        const float* cbase = g_C + (size_t)(b * BR) * I_LEN + colbase;
        float4 cc = *(const float4*)cbase;

        for (int r = 0; r < BR; r++) {
            float4 pf;
            if (r + 1 < BR)
                pf = *(const float4*)(cbase + (size_t)(r + 1) * I_LEN);

            // diag/left-top from previous row
            float dleft = __shfl_up_sync(FULLM, lastD3, 1);
            if (lane == 0) dleft = bprev;

            const float c0 = cc.x, c1 = cc.y, c2 = cc.z, c3 = cc.w;
            float e0 = fminf(dleft, Dp0) + c0;
            float e1 = fminf(Dp0, Dp1) + c1;
            float e2 = fminf(Dp1, Dp2) + c2;
            float e3 = fminf(Dp2, Dp3) + c3;

            float Cl = c0 + c1 + c2 + c3;
            float El = e0;
            El = fminf(El + c1, e1);
            El = fminf(El + c2, e2);
            El = fminf(El + c3, e3);

#pragma unroll
            for (int off = 1; off < 32; off <<= 1) {
                float Cu = __shfl_up_sync(FULLM, Cl, off);
                float Eu = __shfl_up_sync(FULLM, El, off);
                if (lane >= off) {
                    El = fminf(Eu + Cl, El);
                    Cl = Cu + Cl;
                }
            }
            float exC = __shfl_up_sync(FULLM, Cl, 1);
            float exE = __shfl_up_sync(FULLM, El, 1);
            if (lane == 0) { exC = 0.0f; exE = INF; }

            // warp-left boundary D[r][segleft-1]
            float Dleft;
            if (w == 0) {
                Dleft = Dl[sel][r];
            } else {
                unsigned v = slot[w - 1][r];
                while (v == CANARY) v = slot[w - 1][r];
                Dleft = __uint_as_float(v);
            }

            float Din = fminf(exE, Dleft + exC);
            float D0 = fminf(Din + c0, e0);
            float D1 = fminf(D0 + c1, e1);
            float D2 = fminf(D1 + c2, e2);
            float D3 = fminf(D2 + c3, e3);

            if (lane == 31) {
                if (w < 3) slot[w][r] = __float_as_uint(D3);
                else       Dl[sel ^ 1][r] = D3;     // right edge of chunk
            }
            if (r == BR - 1) {
                if (b < NB - 1)
                    *(float4*)(&g_row[b][colbase]) = make_float4(D0, D1, D2, D3);
                res = D3;
            }

            bprev = Dleft;       // this row's warp-left = next row's diag
            lastD3 = D3;
            Dp0 = D0; Dp1 = D1; Dp2 = D2; Dp3 = D3;
            cc = pf;
        }
        __syncthreads();   // chunk end: Dl complete, slots consumed

        if (b < NB - 1) {
            __threadfence();
            if (tid == 0)
                asm volatile("st.release.gpu.global.u32 [%0], %1;"
                             :: "l"(&g_flag[b][j]), "r"(1u));
        }
    }

    if (b == NB - 1 && tid == DTH - 1) out[0] = res;
}

// ---------------------------------------------------------------------------
extern "C" void kernel_launch(void* const* d_in, const int* in_sizes, int n_in,
                              void* d_out, int out_size) {
    const float* kern = (const float*)d_in[0];
    const float* x    = (const float*)d_in[1];
    if (n_in >= 2 && in_sizes[0] == I_LEN * DIM && in_sizes[1] == K_LEN * DIM) {
        kern = (const float*)d_in[1];
        x    = (const float*)d_in[0];
    }

    int nwarp_rows = K_LEN + I_LEN;
    norms_kernel<<<(nwarp_rows + 7) / 8, 256>>>(kern, x);

    dim3 grid(I_LEN / BN, K_LEN / BM);
    cost_gemm<<<grid, 256>>>(kern, x);

    dtw_wave<<<NB, DTH>>>((float*)d_out, out_size);
}